// round 11
// baseline (speedup 1.0000x reference)
#include <cuda_runtime.h>

#define NQ 4
#define NL 2

typedef unsigned long long u64;

// ---------------- packed f32x2 helpers (sm_103a) ----------------
__device__ __forceinline__ u64 pk2(float lo, float hi) {
    u64 r;
    asm("mov.b64 %0, {%1, %2};" : "=l"(r) : "f"(lo), "f"(hi));
    return r;
}
__device__ __forceinline__ void unpk2(u64 v, float& lo, float& hi) {
    asm("mov.b64 {%0, %1}, %2;" : "=f"(lo), "=f"(hi) : "l"(v));
}
__device__ __forceinline__ u64 mul2(u64 a, u64 b) {
    u64 r;
    asm("mul.rn.f32x2 %0, %1, %2;" : "=l"(r) : "l"(a), "l"(b));
    return r;
}
__device__ __forceinline__ u64 add2(u64 a, u64 b) {
    u64 r;
    asm("add.rn.f32x2 %0, %1, %2;" : "=l"(r) : "l"(a), "l"(b));
    return r;
}
__device__ __forceinline__ u64 sub2(u64 a, u64 b) {
    u64 r;
    asm("sub.rn.f32x2 %0, %1, %2;" : "=l"(r) : "l"(a), "l"(b));
    return r;
}
__device__ __forceinline__ u64 fma2(u64 a, u64 b, u64 c) {
    u64 r;
    asm("fma.rn.f32x2 %0, %1, %2, %3;" : "=l"(r) : "l"(a), "l"(b), "l"(c));
    return r;
}

// Batch-invariant constants (both f32x2 lanes duplicated).
//  - Layer-0 RYs in tan form; scalar C'=prod cos(w0/2) folded as C'^2 into coeffs.
//  - Layer-1 RYs absorbed: RY(th)^T Z RY(th) = cos(th) Z - sin(th) X.
//  - h is odd under s -> s^15 (full bit complement), so only s=0..7 stored:
//      sum_s h[s] p_s = sum_{s<8} h[s] (p_s - p_{s^15})
struct Consts {
    u64 tp[NQ];    // (+tan(w0_i/2))
    u64 tn[NQ];    // (-tan(w0_i/2))
    u64 hf0[8];    // folded Z-part coeffs (s=0..7), head row 0
    u64 hf1[8];    // folded Z-part coeffs (s=0..7), head row 1
    u64 v0[NQ];    // X-part coeffs, head row 0
    u64 v1[NQ];    // X-part coeffs, head row 1
    u64 b0, b1;
};

__device__ Consts g_scratch;          // written by setup_kernel
__constant__ Consts c_consts;         // filled via D2D memcpy; read via constant port

__global__ void setup_kernel(const float* __restrict__ weights,
                             const float* __restrict__ W,
                             const float* __restrict__ b) {
    if (threadIdx.x == 0 && blockIdx.x == 0) {
        float C = 1.0f;
        for (int i = 0; i < NQ; ++i) {
            float h = 0.5f * weights[i];          // layer 0
            float c = cosf(h), s = sinf(h);
            float t = s / c;
            C *= c;
            g_scratch.tp[i] = pk2(t, t);
            g_scratch.tn[i] = pk2(-t, -t);
        }
        float C2 = C * C;
        float c1[NQ], s1[NQ];
        for (int i = 0; i < NQ; ++i) {
            c1[i] = cosf(weights[NQ + i]);        // layer 1, full angle
            s1[i] = sinf(weights[NQ + i]);
        }
        for (int s = 0; s < 8; ++s) {             // only s=0..7 (odd symmetry)
            float a0 = 0.0f, a1 = 0.0f;
            for (int i = 0; i < NQ; ++i) {
                float sign = ((s >> (3 - i)) & 1) ? -1.0f : 1.0f;
                a0 += W[0 * NQ + i] * c1[i] * sign;
                a1 += W[1 * NQ + i] * c1[i] * sign;
            }
            g_scratch.hf0[s] = pk2(C2 * a0, C2 * a0);
            g_scratch.hf1[s] = pk2(C2 * a1, C2 * a1);
        }
        for (int i = 0; i < NQ; ++i) {
            float u0 = -2.0f * C2 * W[0 * NQ + i] * s1[i];
            float u1 = -2.0f * C2 * W[1 * NQ + i] * s1[i];
            g_scratch.v0[i] = pk2(u0, u0);
            g_scratch.v1[i] = pk2(u1, u1);
        }
        g_scratch.b0 = pk2(b[0], b[0]);
        g_scratch.b1 = pk2(b[1], b[1]);
    }
}

// tan-form RY on qubit q: a0' = a0 - t*a1 ; a1' = a1 + t*a0
__device__ __forceinline__ void ry_tan(u64 a[16], int q, u64 tp, u64 tn) {
    const int m = 1 << (3 - q);
#pragma unroll
    for (int idx = 0; idx < 16; ++idx) {
        if (!(idx & m)) {
            u64 a0 = a[idx];
            u64 a1 = a[idx | m];
            a[idx]     = fma2(tn, a1, a0);
            a[idx | m] = fma2(tp, a0, a1);
        }
    }
}

// CNOT: compile-time register permutation (zero instructions after unroll).
__device__ __forceinline__ void cnot2(u64 a[16], int ctrl, int tgt) {
    const int mc = 1 << (3 - ctrl);
    const int mt = 1 << (3 - tgt);
#pragma unroll
    for (int s = 0; s < 16; ++s) {
        if ((s & mc) && !(s & mt)) {
            u64 tmp = a[s];
            a[s] = a[s | mt];
            a[s | mt] = tmp;
        }
    }
}

__global__ __launch_bounds__(128)
void sim_kernel(const float4* __restrict__ x, float4* __restrict__ out, int Bpair) {
    int t = blockIdx.x * blockDim.x + threadIdx.x;
    if (t >= Bpair) return;

    float4 xa = x[2 * t];
    float4 xb = x[2 * t + 1];

    float c0a, s0a, c1a, s1a, c2a, s2a, c3a, s3a;
    float c0b, s0b, c1b, s1b, c2b, s2b, c3b, s3b;
    __sincosf(0.5f * xa.x, &s0a, &c0a);
    __sincosf(0.5f * xa.y, &s1a, &c1a);
    __sincosf(0.5f * xa.z, &s2a, &c2a);
    __sincosf(0.5f * xa.w, &s3a, &c3a);
    __sincosf(0.5f * xb.x, &s0b, &c0b);
    __sincosf(0.5f * xb.y, &s1b, &c1b);
    __sincosf(0.5f * xb.z, &s2b, &c2b);
    __sincosf(0.5f * xb.w, &s3b, &c3b);

    u64 c0 = pk2(c0a, c0b), s0 = pk2(s0a, s0b);
    u64 c1 = pk2(c1a, c1b), s1 = pk2(s1a, s1b);
    u64 c2 = pk2(c2a, c2b), s2 = pk2(s2a, s2b);
    u64 c3 = pk2(c3a, c3b), s3 = pk2(s3a, s3b);

    // Product state via balanced pair tree (24 muls, depth 2 after MUFU).
    u64 t01[4], t23[4];
    t01[0] = mul2(c0, c1);  t01[1] = mul2(c0, s1);
    t01[2] = mul2(s0, c1);  t01[3] = mul2(s0, s1);
    t23[0] = mul2(c2, c3);  t23[1] = mul2(c2, s3);
    t23[2] = mul2(s2, c3);  t23[3] = mul2(s2, s3);

    u64 a[16];
#pragma unroll
    for (int s = 0; s < 16; ++s) {
        a[s] = mul2(t01[s >> 2], t23[s & 3]);
    }

    // Layer 0: CNOT ring (free) + tan-form RYs.
    cnot2(a, 0, 1);
    cnot2(a, 1, 2);
    cnot2(a, 2, 3);
    cnot2(a, 3, 0);
#pragma unroll
    for (int q = 0; q < NQ; ++q) {
        ry_tan(a, q, c_consts.tp[q], c_consts.tn[q]);
    }

    // Layer 1: CNOT ring (free); RYs absorbed into the measurement below.
    cnot2(a, 0, 1);
    cnot2(a, 1, 2);
    cnot2(a, 2, 3);
    cnot2(a, 3, 0);

    // Measurement, Z part via odd symmetry: only 8 coefficients per row.
    //   o_j = b_j + sum_{s<8} hf_j[s] (p_s - p_{s^15}) + sum_i v_j[i] y_i
    u64 acc0 = c_consts.b0;
    u64 acc1 = c_consts.b1;
#pragma unroll
    for (int s = 0; s < 8; ++s) {
        u64 d = sub2(mul2(a[s], a[s]), mul2(a[s ^ 15], a[s ^ 15]));
        acc0 = fma2(c_consts.hf0[s], d, acc0);
        acc1 = fma2(c_consts.hf1[s], d, acc1);
    }

    // Cross terms y_i = sum over pairs a_s a_{s^m_i}.
#pragma unroll
    for (int i = 0; i < NQ; ++i) {
        const int m = 8 >> i;
        u64 y;
        bool first = true;
#pragma unroll
        for (int s = 0; s < 16; ++s) {
            if (!(s & m)) {
                if (first) { y = mul2(a[s], a[s | m]); first = false; }
                else       { y = fma2(a[s], a[s | m], y); }
            }
        }
        acc0 = fma2(c_consts.v0[i], y, acc0);
        acc1 = fma2(c_consts.v1[i], y, acc1);
    }

    float o0a, o0b, o1a, o1b;
    unpk2(acc0, o0a, o0b);
    unpk2(acc1, o1a, o1b);

    out[t] = make_float4(o0a, o1a, o0b, o1b);
}

extern "C" void kernel_launch(void* const* d_in, const int* in_sizes, int n_in,
                              void* d_out, int out_size) {
    const float* x       = (const float*)d_in[0];  // (B, 4)
    const float* weights = (const float*)d_in[1];  // (2, 4)
    const float* W       = (const float*)d_in[2];  // (2, 4)
    const float* b       = (const float*)d_in[3];  // (2,)

    int B = in_sizes[0] / NQ;
    int Bpair = B / 2;

    setup_kernel<<<1, 32>>>(weights, W, b);

    void* dst = nullptr;
    void* src = nullptr;
    cudaGetSymbolAddress(&dst, c_consts);
    cudaGetSymbolAddress(&src, g_scratch);
    cudaMemcpyAsync(dst, src, sizeof(Consts), cudaMemcpyDeviceToDevice, 0);

    sim_kernel<<<(Bpair + 127) / 128, 128>>>((const float4*)x, (float4*)d_out, Bpair);
}

// round 12
// speedup vs baseline: 1.2600x; 1.2600x over previous
#include <cuda_runtime.h>

typedef unsigned long long u64;

// ---------------- packed f32x2 helpers (sm_103a) ----------------
__device__ __forceinline__ u64 pk2(float lo, float hi) {
    u64 r;
    asm("mov.b64 %0, {%1, %2};" : "=l"(r) : "f"(lo), "f"(hi));
    return r;
}
__device__ __forceinline__ void unpk2(u64 v, float& lo, float& hi) {
    asm("mov.b64 {%0, %1}, %2;" : "=f"(lo), "=f"(hi) : "l"(v));
}
__device__ __forceinline__ u64 mul2(u64 a, u64 b) {
    u64 r;
    asm("mul.rn.f32x2 %0, %1, %2;" : "=l"(r) : "l"(a), "l"(b));
    return r;
}
__device__ __forceinline__ u64 fma2(u64 a, u64 b, u64 c) {
    u64 r;
    asm("fma.rn.f32x2 %0, %1, %2, %3;" : "=l"(r) : "l"(a), "l"(b), "l"(c));
    return r;
}

// Heisenberg-picture constants. Each feature <Z_q> is an exact multilinear
// polynomial in (1, cos x_i, sin x_i); Pauli back-propagation gives the sparse
// monomial support (6/5/6/13 terms). Coefficients are extracted numerically in
// setup_kernel via exact 3^4-grid interpolation.
struct Consts {
    u64 k0[6];
    u64 k1[5];
    u64 k2[6];
    u64 k3[13];
    u64 w0[4], w1[4];   // head rows (packed)
    u64 b0, b1;         // bias + (analytically zero) constant-term fold
};

__device__ Consts g_scratch;
__constant__ Consts c_consts;

__global__ void setup_kernel(const float* __restrict__ weights,
                             const float* __restrict__ W,
                             const float* __restrict__ b) {
    __shared__ float G[4][81];
    int tid = threadIdx.x;

    // --- 1. simulate circuit features on the 3^4 grid x_i in {0, pi/2, pi} ---
    if (tid < 81) {
        const float HP = 1.57079632679489662f;  // pi/2
        int d0 = tid / 27, d1 = (tid / 9) % 3, d2 = (tid / 3) % 3, d3 = tid % 3;
        float xg[4] = { d0 * HP, d1 * HP, d2 * HP, d3 * HP };
        float cc[4], ss[4];
        for (int i = 0; i < 4; ++i) {
            float h = 0.5f * xg[i];
            cc[i] = cosf(h);
            ss[i] = sinf(h);
        }
        float st[16];
        for (int s = 0; s < 16; ++s) {
            float v = 1.0f;
            for (int i = 0; i < 4; ++i) v *= ((s >> (3 - i)) & 1) ? ss[i] : cc[i];
            st[s] = v;
        }
        for (int l = 0; l < 2; ++l) {
            for (int i = 0; i < 4; ++i) {               // CNOT ring
                int c = i, tq = (i + 1) & 3;
                int mc = 1 << (3 - c), mt = 1 << (3 - tq);
                for (int s = 0; s < 16; ++s)
                    if ((s & mc) && !(s & mt)) {
                        float tmp = st[s]; st[s] = st[s | mt]; st[s | mt] = tmp;
                    }
            }
            for (int i = 0; i < 4; ++i) {               // RY(weights[l][i])
                float h = 0.5f * weights[l * 4 + i];
                float c = cosf(h), sn = sinf(h);
                int m = 1 << (3 - i);
                for (int s = 0; s < 16; ++s)
                    if (!(s & m)) {
                        float a0 = st[s], a1 = st[s | m];
                        st[s]     = c * a0 - sn * a1;
                        st[s | m] = sn * a0 + c * a1;
                    }
            }
        }
        for (int q = 0; q < 4; ++q) {
            int m = 1 << (3 - q);
            float f = 0.0f;
            for (int s = 0; s < 16; ++s) {
                float p = st[s] * st[s];
                f += (s & m) ? -p : p;
            }
            G[q][tid] = f;
        }
    }
    __syncthreads();

    // --- 2. exact per-axis inverse transform: values(0,pi/2,pi) -> (1,cos,sin) coeffs ---
    for (int a = 0; a < 4; ++a) {
        int stride = (a == 0) ? 27 : (a == 1) ? 9 : (a == 2) ? 3 : 1;
        if (tid < 108) {
            int q = tid / 27, line = tid % 27;
            int e0 = line / 9, e1 = (line / 3) % 3, e2 = line % 3;
            int digs[4];
            int ej[3] = { e0, e1, e2 };
            int j = 0;
            for (int pos = 0; pos < 4; ++pos)
                digs[pos] = (pos == a) ? 0 : ej[j++];
            int p0 = digs[0] * 27 + digs[1] * 9 + digs[2] * 3 + digs[3];
            float g0 = G[q][p0], g1 = G[q][p0 + stride], g2 = G[q][p0 + 2 * stride];
            float k1v = 0.5f * (g0 + g2);
            float kcv = 0.5f * (g0 - g2);
            float ksv = g1 - k1v;
            G[q][p0] = k1v;
            G[q][p0 + stride] = kcv;
            G[q][p0 + 2 * stride] = ksv;
        }
        __syncthreads();
    }

    // --- 3. pick sparse monomial coefficients + fold head ---
    if (tid == 0) {
        // monomial tensor indices: digit per qubit (27,9,3,1): 0="1", 1="cos", 2="sin"
        const int i0[6]  = { 37, 77, 25, 54, 60, 31 };  // c0c1c3, s0s1c2s3, s1s2c3, s0, s0s2, c0c2c3
        const int i1[5]  = { 31, 60, 20, 44, 3 };       // c0c2c3, s0s2, s1s3, c0c1s2s3, c2
        const int i2[6]  = { 10, 52, 75, 56, 78, 1 };   // c1c3, c0s1s2c3, s0s1c2, s0s3, s0s1s2, c3
        const int i3[13] = { 30, 17, 47, 67, 5, 42, 61, 18, 9, 51, 76, 38, 26 };
        // c0c2, c1s2s3, c0s1s3, s0c1c2c3, c2s3, c0c1s2, s0s2c3, s1, c1, c0s1s2, s0s1c2c3, c0c1s3, s1s2s3
        for (int i = 0; i < 6; ++i)  g_scratch.k0[i] = pk2(G[0][i0[i]], G[0][i0[i]]);
        for (int i = 0; i < 5; ++i)  g_scratch.k1[i] = pk2(G[1][i1[i]], G[1][i1[i]]);
        for (int i = 0; i < 6; ++i)  g_scratch.k2[i] = pk2(G[2][i2[i]], G[2][i2[i]]);
        for (int i = 0; i < 13; ++i) g_scratch.k3[i] = pk2(G[3][i3[i]], G[3][i3[i]]);
        for (int q = 0; q < 4; ++q) {
            g_scratch.w0[q] = pk2(W[q], W[q]);
            g_scratch.w1[q] = pk2(W[4 + q], W[4 + q]);
        }
        float cb0 = b[0] + W[0] * G[0][0] + W[1] * G[1][0] + W[2] * G[2][0] + W[3] * G[3][0];
        float cb1 = b[1] + W[4] * G[0][0] + W[5] * G[1][0] + W[6] * G[2][0] + W[7] * G[3][0];
        g_scratch.b0 = pk2(cb0, cb0);
        g_scratch.b1 = pk2(cb1, cb1);
    }
}

__global__ __launch_bounds__(128)
void sim_kernel(const float4* __restrict__ x, float4* __restrict__ out, int Bpair) {
    int t = blockIdx.x * blockDim.x + threadIdx.x;
    if (t >= Bpair) return;

    float4 xa = x[2 * t];
    float4 xb = x[2 * t + 1];

    // Full-angle sincos (features are multilinear in cos x_i, sin x_i).
    float c0a, s0a, c1a, s1a, c2a, s2a, c3a, s3a;
    float c0b, s0b, c1b, s1b, c2b, s2b, c3b, s3b;
    __sincosf(xa.x, &s0a, &c0a);
    __sincosf(xa.y, &s1a, &c1a);
    __sincosf(xa.z, &s2a, &c2a);
    __sincosf(xa.w, &s3a, &c3a);
    __sincosf(xb.x, &s0b, &c0b);
    __sincosf(xb.y, &s1b, &c1b);
    __sincosf(xb.z, &s2b, &c2b);
    __sincosf(xb.w, &s3b, &c3b);

    u64 C0 = pk2(c0a, c0b), S0 = pk2(s0a, s0b);
    u64 C1 = pk2(c1a, c1b), S1 = pk2(s1a, s1b);
    u64 C2 = pk2(c2a, c2b), S2 = pk2(s2a, s2b);
    u64 C3 = pk2(c3a, c3b), S3 = pk2(s3a, s3b);

    // Shared pair products.
    u64 c0c1 = mul2(C0, C1), s0s1 = mul2(S0, S1);
    u64 c2c3 = mul2(C2, C3), s2s3 = mul2(S2, S3);
    u64 s1s2 = mul2(S1, S2), s1s3 = mul2(S1, S3);
    u64 s0s2 = mul2(S0, S2), c1c3 = mul2(C1, C3);
    u64 c0c2 = mul2(C0, C2), c0s1 = mul2(C0, S1);
    u64 c2s3 = mul2(C2, S3), s0s3 = mul2(S0, S3);

    u64 m6v = mul2(c0c2, C3);            // c0c2c3 (shared F0/F1)
    u64 c0s1s2 = mul2(c0s1, S2);         // shared F2/F3

    // F0 = <Z0>: c0c1c3, s0s1c2s3, s1s2c3, s0, s0s2, c0c2c3
    u64 F0 = mul2(c_consts.k0[0], mul2(c0c1, C3));
    F0 = fma2(c_consts.k0[1], mul2(s0s1, c2s3), F0);
    F0 = fma2(c_consts.k0[2], mul2(s1s2, C3), F0);
    F0 = fma2(c_consts.k0[3], S0, F0);
    F0 = fma2(c_consts.k0[4], s0s2, F0);
    F0 = fma2(c_consts.k0[5], m6v, F0);

    // F1 = <Z1>: c0c2c3, s0s2, s1s3, c0c1s2s3, c2
    u64 F1 = mul2(c_consts.k1[0], m6v);
    F1 = fma2(c_consts.k1[1], s0s2, F1);
    F1 = fma2(c_consts.k1[2], s1s3, F1);
    F1 = fma2(c_consts.k1[3], mul2(c0c1, s2s3), F1);
    F1 = fma2(c_consts.k1[4], C2, F1);

    // F2 = <Z2>: c1c3, c0s1s2c3, s0s1c2, s0s3, s0s1s2, c3
    u64 F2 = mul2(c_consts.k2[0], c1c3);
    F2 = fma2(c_consts.k2[1], mul2(c0s1s2, C3), F2);
    F2 = fma2(c_consts.k2[2], mul2(s0s1, C2), F2);
    F2 = fma2(c_consts.k2[3], s0s3, F2);
    F2 = fma2(c_consts.k2[4], mul2(s0s1, S2), F2);
    F2 = fma2(c_consts.k2[5], C3, F2);

    // F3 = <Z3>: c0c2, c1s2s3, c0s1s3, s0c1c2c3, c2s3, c0c1s2, s0s2c3,
    //            s1, c1, c0s1s2, s0s1c2c3, c0c1s3, s1s2s3
    u64 F3 = mul2(c_consts.k3[0], c0c2);
    F3 = fma2(c_consts.k3[1], mul2(C1, s2s3), F3);
    F3 = fma2(c_consts.k3[2], mul2(c0s1, S3), F3);
    F3 = fma2(c_consts.k3[3], mul2(S0, mul2(C1, c2c3)), F3);
    F3 = fma2(c_consts.k3[4], c2s3, F3);
    F3 = fma2(c_consts.k3[5], mul2(c0c1, S2), F3);
    F3 = fma2(c_consts.k3[6], mul2(s0s2, C3), F3);
    F3 = fma2(c_consts.k3[7], S1, F3);
    F3 = fma2(c_consts.k3[8], C1, F3);
    F3 = fma2(c_consts.k3[9], c0s1s2, F3);
    F3 = fma2(c_consts.k3[10], mul2(s0s1, c2c3), F3);
    F3 = fma2(c_consts.k3[11], mul2(c0c1, S3), F3);
    F3 = fma2(c_consts.k3[12], mul2(s1s2, S3), F3);

    // Head: out_j = b_j' + sum_q W_jq F_q
    u64 o0 = fma2(c_consts.w0[0], F0, c_consts.b0);
    o0 = fma2(c_consts.w0[1], F1, o0);
    o0 = fma2(c_consts.w0[2], F2, o0);
    o0 = fma2(c_consts.w0[3], F3, o0);
    u64 o1 = fma2(c_consts.w1[0], F0, c_consts.b1);
    o1 = fma2(c_consts.w1[1], F1, o1);
    o1 = fma2(c_consts.w1[2], F2, o1);
    o1 = fma2(c_consts.w1[3], F3, o1);

    float o0a, o0b, o1a, o1b;
    unpk2(o0, o0a, o0b);
    unpk2(o1, o1a, o1b);

    out[t] = make_float4(o0a, o1a, o0b, o1b);
}

extern "C" void kernel_launch(void* const* d_in, const int* in_sizes, int n_in,
                              void* d_out, int out_size) {
    const float* x       = (const float*)d_in[0];  // (B, 4)
    const float* weights = (const float*)d_in[1];  // (2, 4)
    const float* W       = (const float*)d_in[2];  // (2, 4)
    const float* b       = (const float*)d_in[3];  // (2,)

    int B = in_sizes[0] / 4;
    int Bpair = B / 2;

    setup_kernel<<<1, 128>>>(weights, W, b);

    void* dst = nullptr;
    void* src = nullptr;
    cudaGetSymbolAddress(&dst, c_consts);
    cudaGetSymbolAddress(&src, g_scratch);
    cudaMemcpyAsync(dst, src, sizeof(Consts), cudaMemcpyDeviceToDevice, 0);

    sim_kernel<<<(Bpair + 127) / 128, 128>>>((const float4*)x, (float4*)d_out, Bpair);
}